// round 15
// baseline (speedup 1.0000x reference)
#include <cuda_runtime.h>
#include <cuda_fp16.h>
#include <math.h>
#include <cstdint>

#define B_  64
#define T_  218
#define D_  512
#define R_  (B_*T_)      // 13952
#define H_  4
#define DK_ 128
#define QKVW (3*D_)      // 1536

// ---------------- scratch ----------------------------------------------------
__device__ __half g_h[R_*D_];
__device__ __half g_qkv[R_*QKVW];
__device__ __half g_vm[R_*D_];
__device__ float  g_fsmn[R_*D_];
__device__ __half g_ctx[R_*D_];
__device__ float  g_x1[R_*D_];
__device__ __half g_mid[R_*2048];
__device__ __half g_qkv_wt[QKVW*D_];
__device__ __half g_out_wt[D_*D_];
__device__ __half g_w1t[2048*D_];
__device__ __half g_w2t[D_*2048];
__device__ __half g_kwt[11*D_*D_];

// ---------------- helpers ----------------------------------------------------
__device__ __forceinline__ uint32_t smem_u32(const void* p) {
    uint32_t a;
    asm("{ .reg .u64 t; cvta.to.shared.u64 t, %1; cvt.u32.u64 %0, t; }" : "=r"(a) : "l"(p));
    return a;
}
__device__ __forceinline__ void cp16(uint32_t dst, const void* src, bool pred) {
    int sz = pred ? 16 : 0;
    asm volatile("cp.async.cg.shared.global [%0], [%1], 16, %2;"
                 :: "r"(dst), "l"(src), "r"(sz) : "memory");
}
#define CP_COMMIT() asm volatile("cp.async.commit_group;" ::: "memory")
#define CP_WAIT1()  asm volatile("cp.async.wait_group 1;" ::: "memory")
#define CP_WAIT0()  asm volatile("cp.async.wait_group 0;" ::: "memory")

#define MMAH(d, a0, a1, a2, a3, b0, b1) \
    asm volatile("mma.sync.aligned.m16n8k16.row.col.f32.f16.f16.f32 " \
                 "{%0,%1,%2,%3},{%4,%5,%6,%7},{%8,%9},{%0,%1,%2,%3};" \
                 : "+f"((d)[0]), "+f"((d)[1]), "+f"((d)[2]), "+f"((d)[3]) \
                 : "r"(a0), "r"(a1), "r"(a2), "r"(a3), "r"(b0), "r"(b1))

#define LDSM4(r0, r1, r2, r3, addr) \
    asm volatile("ldmatrix.sync.aligned.m8n8.x4.shared.b16 {%0,%1,%2,%3}, [%4];" \
                 : "=r"(r0), "=r"(r1), "=r"(r2), "=r"(r3) : "r"(addr))

#define KT  64
#define LDWH 72
#define MTSTEP (16*LDWH*2)              // 2304

// hgemm (64x128 tile) smem layout
#define ATILEB (64*LDWH*2)              // 9216
#define BTILEB (128*LDWH*2)             // 18432
#define STG (ATILEB+BTILEB)             // 27648
#define DSMEM_G (2*STG)                 // 55296

// conv_att (128x128 tile) smem layout
#define TILEH (128*LDWH)
#define DSMEM_CA (4*TILEH*2)            // 73728

// attention smem layout (inside conv_att smem)
#define QT2 64
#define LQ  136
#define LSC 232
#define LVT 40
#define OFF_K   (QT2*LQ)
#define OFF_VT  (OFF_K + 32*LQ)
#define OFF_SC  (OFF_VT + 128*LVT)

#define CONVBLKS 436

// ---------------- merged prep: 4 transposes + kw + LN0 ----------------------
__device__ __forceinline__ void do_transpose(const float* __restrict__ src,
                                             __half* __restrict__ dst,
                                             int Kd, int Nd, int nbx, int lbid,
                                             float* tile, int tid) {
    int bx = lbid % nbx, by = lbid / nbx;
    int k0 = by * 32, n0 = bx * 32;
    int x = tid & 31, y = tid >> 5;
#pragma unroll
    for (int i = 0; i < 32; i += 8)
        tile[(y + i) * 33 + x] = src[(size_t)(k0 + y + i) * Nd + n0 + x];
    __syncthreads();
#pragma unroll
    for (int i = 0; i < 32; i += 8)
        dst[(size_t)(n0 + y + i) * Kd + k0 + x] = __float2half(tile[x * 33 + y + i]);
}

__global__ void __launch_bounds__(256)
prep_kernel(const float* __restrict__ qkv_w, const float* __restrict__ out_w,
            const float* __restrict__ w1, const float* __restrict__ w2,
            const float* __restrict__ fw,
            const float* __restrict__ x, const float* __restrict__ ln0_w,
            const float* __restrict__ ln0_b) {
    __shared__ float tile[32 * 33];
    __shared__ float red[16];
    int bid = blockIdx.x;
    int tid = threadIdx.x;
    if (bid < 768) {
        do_transpose(qkv_w, g_qkv_wt, D_, QKVW, 48, bid, tile, tid);
    } else if (bid < 1024) {
        do_transpose(out_w, g_out_wt, D_, D_, 16, bid - 768, tile, tid);
    } else if (bid < 2048) {
        do_transpose(w1, g_w1t, D_, 2048, 64, bid - 1024, tile, tid);
    } else if (bid < 3072) {
        do_transpose(w2, g_w2t, 2048, D_, 16, bid - 2048, tile, tid);
    } else if (bid < 14336) {
        int idx = (bid - 3072) * 256 + tid;
        int tap = idx / (D_ * D_);
        int rem = idx % (D_ * D_);
        int dout = rem / D_;
        int din = rem % D_;
        g_kwt[idx] = __float2half(fw[((size_t)dout * D_ + din) * 11 + tap]);
    } else {
        int row = bid - 14336;
        const float* xr = x + (size_t)row * D_;
        __half* orow = g_h + (size_t)row * D_;
        float v0 = xr[tid], v1 = xr[tid + 256];
        float s = v0 + v1, sq = v0 * v0 + v1 * v1;
#pragma unroll
        for (int o = 16; o; o >>= 1) {
            s  += __shfl_xor_sync(~0u, s, o);
            sq += __shfl_xor_sync(~0u, sq, o);
        }
        int lane = tid & 31, wid = tid >> 5;
        if (lane == 0) { red[wid] = s; red[8 + wid] = sq; }
        __syncthreads();
        if (tid == 0) {
            float S = 0.f, SQ = 0.f;
#pragma unroll
            for (int i = 0; i < 8; i++) { S += red[i]; SQ += red[8 + i]; }
            float mean = S * (1.f / D_);
            float var = SQ * (1.f / D_) - mean * mean;
            red[0] = mean;
            red[1] = rsqrtf(var + 1e-5f);
        }
        __syncthreads();
        float mean = red[0], inv = red[1];
        orow[tid]       = __float2half((v0 - mean) * inv * ln0_w[tid] + ln0_b[tid]);
        orow[tid + 256] = __float2half((v1 - mean) * inv * ln0_w[tid + 256] + ln0_b[tid + 256]);
    }
}

// ---------------- layer norm (half output) ----------------------------------
__global__ void ln_kernel(const float* __restrict__ x, const float* __restrict__ w,
                          const float* __restrict__ b, __half* __restrict__ out) {
    int row = blockIdx.x;
    const float* xr = x + (size_t)row * D_;
    __half* orow = out + (size_t)row * D_;
    float v[4];
    float s = 0.f, sq = 0.f;
#pragma unroll
    for (int i = 0; i < 4; i++) {
        v[i] = xr[threadIdx.x + i * 128];
        s += v[i]; sq += v[i] * v[i];
    }
    __shared__ float sm[8];
#pragma unroll
    for (int o = 16; o; o >>= 1) {
        s  += __shfl_xor_sync(~0u, s, o);
        sq += __shfl_xor_sync(~0u, sq, o);
    }
    int lane = threadIdx.x & 31, wid = threadIdx.x >> 5;
    if (lane == 0) { sm[wid] = s; sm[4 + wid] = sq; }
    __syncthreads();
    if (threadIdx.x == 0) {
        float S = sm[0] + sm[1] + sm[2] + sm[3];
        float SQ = sm[4] + sm[5] + sm[6] + sm[7];
        float mean = S * (1.f / D_);
        float var = SQ * (1.f / D_) - mean * mean;
        sm[0] = mean;
        sm[1] = rsqrtf(var + 1e-5f);
    }
    __syncthreads();
    float mean = sm[0], inv = sm[1];
#pragma unroll
    for (int i = 0; i < 4; i++) {
        int c = threadIdx.x + i * 128;
        orow[c] = __float2half((v[i] - mean) * inv * w[c] + b[c]);
    }
}

// ---------------- fp16 mma GEMM: 64x128 CTA, 32x32 warp tile, 3 CTA/SM ------
// epi: 0=bias->Cf; 1=bias+relu->Ch; 2=bias+add1+add2->Cf; 3=bias+add1->Cf;
//      4=bias->Ch; 5=bias->Ch(qkv) + v-cols also vm=half(v*m)
__global__ void __launch_bounds__(256, 3)
hgemm(const __half* __restrict__ A, const __half* __restrict__ Bt,
      const float* __restrict__ bias, float* __restrict__ Cf, __half* __restrict__ Ch,
      int N, int K, int epi,
      const float* __restrict__ add1, const float* __restrict__ add2,
      __half* __restrict__ vmout) {
    extern __shared__ __half smh[];
    uint32_t smB = smem_u32(smh);
    int tid = threadIdx.x;
    int lane = tid & 31, wid = tid >> 5;
    int wm = (wid & 1) * 32;            // M half (64 rows total)
    int wn = (wid >> 1) * 32;           // N quarter (128 cols total)
    int g = lane >> 2, c = lane & 3;
    int rowBase = blockIdx.y * 64, colBase = blockIdx.x * 128;

    // staging: A tile 64x64h = 512 chunks (2/thread); B tile 128x64h = 1024 (4/thread)
    int srA[2], ssA[2], srB[4], ssB[4];
#pragma unroll
    for (int u = 0; u < 2; u++) {
        int f = tid + 256 * u;
        srA[u] = f >> 3; ssA[u] = f & 7;
    }
#pragma unroll
    for (int u = 0; u < 4; u++) {
        int f = tid + 256 * u;
        srB[u] = f >> 3; ssB[u] = f & 7;
    }

    int laneRowA = (lane & 7) + ((lane >> 3) & 1) * 8;
    int laneKA   = (lane >> 4) * 8;
    int laneRowB = (lane & 7) + ((lane >> 4) & 1) * 8;
    int laneKB   = ((lane >> 3) & 1) * 8;
    uint32_t aBase = smB + ((wm + laneRowA) * LDWH + laneKA) * 2;
    uint32_t bBase = smB + ATILEB + ((wn + laneRowB) * LDWH + laneKB) * 2;

    float acc[2][4][4];
#pragma unroll
    for (int i = 0; i < 2; i++)
#pragma unroll
        for (int j = 0; j < 4; j++)
#pragma unroll
            for (int q = 0; q < 4; q++) acc[i][j][q] = 0.f;

    int nk = K >> 6;
    const __half* Arow = A + (size_t)rowBase * K;
    const __half* Brow = Bt + (size_t)colBase * K;

    // stage 0
#pragma unroll
    for (int u = 0; u < 2; u++)
        cp16(smB + (uint32_t)(srA[u] * LDWH + ssA[u] * 8) * 2,
             Arow + (size_t)srA[u] * K + ssA[u] * 8, true);
#pragma unroll
    for (int u = 0; u < 4; u++)
        cp16(smB + ATILEB + (uint32_t)(srB[u] * LDWH + ssB[u] * 8) * 2,
             Brow + (size_t)srB[u] * K + ssB[u] * 8, true);
    CP_COMMIT();

    for (int kt = 0; kt < nk; kt++) {
        uint32_t buf = (kt & 1) ? STG : 0;
        if (kt + 1 < nk) {
            uint32_t nb = ((kt + 1) & 1) ? STG : 0;
            const __half* Ag = Arow + (size_t)(kt + 1) * KT;
            const __half* Bg = Brow + (size_t)(kt + 1) * KT;
#pragma unroll
            for (int u = 0; u < 2; u++)
                cp16(smB + nb + (uint32_t)(srA[u] * LDWH + ssA[u] * 8) * 2,
                     Ag + (size_t)srA[u] * K + ssA[u] * 8, true);
#pragma unroll
            for (int u = 0; u < 4; u++)
                cp16(smB + nb + ATILEB + (uint32_t)(srB[u] * LDWH + ssB[u] * 8) * 2,
                     Bg + (size_t)srB[u] * K + ssB[u] * 8, true);
            CP_COMMIT();
            CP_WAIT1();
        } else {
            CP_WAIT0();
        }
        __syncthreads();
        uint32_t aB = aBase + buf, bB = bBase + buf;
#pragma unroll
        for (int ks = 0; ks < 4; ks++) {
            uint32_t a0r[4], a1r[4], b0r[4], b1r[4];
            LDSM4(a0r[0], a0r[1], a0r[2], a0r[3], aB + ks * 32);
            LDSM4(a1r[0], a1r[1], a1r[2], a1r[3], aB + MTSTEP + ks * 32);
            LDSM4(b0r[0], b0r[1], b0r[2], b0r[3], bB + ks * 32);
            LDSM4(b1r[0], b1r[1], b1r[2], b1r[3], bB + MTSTEP + ks * 32);
            MMAH(acc[0][0], a0r[0], a0r[1], a0r[2], a0r[3], b0r[0], b0r[1]);
            MMAH(acc[0][1], a0r[0], a0r[1], a0r[2], a0r[3], b0r[2], b0r[3]);
            MMAH(acc[0][2], a0r[0], a0r[1], a0r[2], a0r[3], b1r[0], b1r[1]);
            MMAH(acc[0][3], a0r[0], a0r[1], a0r[2], a0r[3], b1r[2], b1r[3]);
            MMAH(acc[1][0], a1r[0], a1r[1], a1r[2], a1r[3], b0r[0], b0r[1]);
            MMAH(acc[1][1], a1r[0], a1r[1], a1r[2], a1r[3], b0r[2], b0r[3]);
            MMAH(acc[1][2], a1r[0], a1r[1], a1r[2], a1r[3], b1r[0], b1r[1]);
            MMAH(acc[1][3], a1r[0], a1r[1], a1r[2], a1r[3], b1r[2], b1r[3]);
        }
        __syncthreads();
    }

#pragma unroll
    for (int mt = 0; mt < 2; mt++) {
#pragma unroll
        for (int nt = 0; nt < 4; nt++) {
            int cb = colBase + wn + nt * 8 + 2 * c;
            float bs0 = bias[cb], bs1 = bias[cb + 1];
#pragma unroll
            for (int half = 0; half < 2; half++) {
                int r = rowBase + wm + mt * 16 + g + half * 8;
                float v0 = acc[mt][nt][half * 2 + 0] + bs0;
                float v1 = acc[mt][nt][half * 2 + 1] + bs1;
                if (epi == 1) {
                    *(__half2*)(Ch + (size_t)r * N + cb) =
                        __floats2half2_rn(fmaxf(v0, 0.f), fmaxf(v1, 0.f));
                    continue;
                } else if (epi == 4) {
                    *(__half2*)(Ch + (size_t)r * N + cb) = __floats2half2_rn(v0, v1);
                    continue;
                } else if (epi == 5) {
                    *(__half2*)(Ch + (size_t)r * N + cb) = __floats2half2_rn(v0, v1);
                    if (cb >= 1024) {
                        float m = add1[r];
                        *(__half2*)(vmout + (size_t)r * 512 + cb - 1024) =
                            __floats2half2_rn(v0 * m, v1 * m);
                    }
                    continue;
                } else if (epi == 2) {
                    size_t id = (size_t)r * 512 + cb;
                    v0 += add1[id] + add2[id];
                    v1 += add1[id + 1] + add2[id + 1];
                } else if (epi == 3) {
                    size_t id = (size_t)r * 512 + cb;
                    v0 += add1[id];
                    v1 += add1[id + 1];
                }
                *(float2*)(Cf + (size_t)r * N + cb) = make_float2(v0, v1);
            }
        }
    }
}

// ---------------- merged conv + attention (unchanged from R14) ---------------
__global__ void __launch_bounds__(256, 2)
conv_att(const __half* __restrict__ vm, const __half* __restrict__ qkv,
         const float* __restrict__ masks, float* __restrict__ out,
         __half* __restrict__ ctx) {
    extern __shared__ __half smh[];
    int tid = threadIdx.x;
    int lane = tid & 31;
    int g = lane >> 2, c = lane & 3;

    if (blockIdx.x < CONVBLKS) {
        __half* Abuf[2] = { smh,         smh + 2 * TILEH };
        __half* Bbuf[2] = { smh + TILEH, smh + 3 * TILEH };
        int wid = tid >> 5;
        int wm = (wid & 3) * 32;
        int wn = (wid >> 2) * 64;
        int colBase = (blockIdx.x & 3) * 128;
        int rowBase = (blockIdx.x >> 2) * 128;

        int srow[4], sseg[4], sb[4], st[4];
#pragma unroll
        for (int u = 0; u < 4; u++) {
            int f = tid + 256 * u;
            srow[u] = f >> 3;
            sseg[u] = f & 7;
            int grow = rowBase + srow[u];
            sb[u] = grow / T_;
            st[u] = grow - sb[u] * T_;
        }

        int laneRowA = (lane & 7) + ((lane >> 3) & 1) * 8;
        int laneKA   = (lane >> 4) * 8;
        int laneRowB = (lane & 7) + ((lane >> 4) & 1) * 8;
        int laneKB   = ((lane >> 3) & 1) * 8;
        uint32_t aOff = ((wm + laneRowA) * LDWH + laneKA) * 2;
        uint32_t bOff = ((wn + laneRowB) * LDWH + laneKB) * 2;
        uint32_t sA[2] = { smem_u32(Abuf[0]) + aOff, smem_u32(Abuf[1]) + aOff };
        uint32_t sB[2] = { smem_u32(Bbuf[0]) + bOff, smem_u32(Bbuf[1]) + bOff };

        float acc[2][8][4];
#pragma unroll
        for (int i = 0; i < 2; i++)
#pragma unroll
            for (int j = 0; j < 8; j++)
#pragma unroll
                for (int q = 0; q < 4; q++) acc[i][j][q] = 0.f;

        const int NT = 11 * 8;
#pragma unroll
        for (int u = 0; u < 4; u++) {
            int src = st[u] - 5;
            bool ok = (unsigned)src < (unsigned)T_;
            cp16(smem_u32(Abuf[0] + srow[u] * LDWH + sseg[u] * 8),
                 vm + ((size_t)(sb[u] * T_ + (ok ? src : 0)) * D_ + sseg[u] * 8), ok);
            cp16(smem_u32(Bbuf[0] + srow[u] * LDWH + sseg[u] * 8),
                 g_kwt + ((size_t)(colBase + srow[u]) * D_ + sseg[u] * 8), true);
        }
        CP_COMMIT();

        for (int ti = 0; ti < NT; ti++) {
            int buf = ti & 1;
            if (ti + 1 < NT) {
                int nb = buf ^ 1;
                int tap = (ti + 1) >> 3, kt = (ti + 1) & 7;
                const __half* Bg = g_kwt + (size_t)tap * D_ * D_ + (size_t)colBase * D_ + kt * KT;
#pragma unroll
                for (int u = 0; u < 4; u++) {
                    int src = st[u] + tap - 5;
                    bool ok = (unsigned)src < (unsigned)T_;
                    cp16(smem_u32(Abuf[nb] + srow[u] * LDWH + sseg[u] * 8),
                         vm + ((size_t)(sb[u] * T_ + (ok ? src : 0)) * D_ + kt * KT + sseg[u] * 8), ok);
                    cp16(smem_u32(Bbuf[nb] + srow[u] * LDWH + sseg[u] * 8),
                         Bg + (size_t)srow[u] * D_ + sseg[u] * 8, true);
                }
                CP_COMMIT();
                CP_WAIT1();
            } else {
                CP_WAIT0();
            }
            __syncthreads();
            uint32_t aB = sA[buf], bB = sB[buf];
#pragma unroll
            for (int ks = 0; ks < 4; ks++) {
                uint32_t a0r[4], a1r[4];
                LDSM4(a0r[0], a0r[1], a0r[2], a0r[3], aB + ks * 32);
                LDSM4(a1r[0], a1r[1], a1r[2], a1r[3], aB + MTSTEP + ks * 32);
#pragma unroll
                for (int np = 0; np < 4; np++) {
                    uint32_t b0, b1, b2, b3;
                    LDSM4(b0, b1, b2, b3, bB + np * MTSTEP + ks * 32);
                    MMAH(acc[0][2 * np],     a0r[0], a0r[1], a0r[2], a0r[3], b0, b1);
                    MMAH(acc[0][2 * np + 1], a0r[0], a0r[1], a0r[2], a0r[3], b2, b3);
                    MMAH(acc[1][2 * np],     a1r[0], a1r[1], a1r[2], a1r[3], b0, b1);
                    MMAH(acc[1][2 * np + 1], a1r[0], a1r[1], a1r[2], a1r[3], b2, b3);
                }
            }
            __syncthreads();
        }

#pragma unroll
        for (int mt = 0; mt < 2; mt++) {
#pragma unroll
            for (int nt = 0; nt < 8; nt++) {
                int cb = colBase + wn + nt * 8 + 2 * c;
#pragma unroll
                for (int half = 0; half < 2; half++) {
                    int r = rowBase + wm + mt * 16 + g + half * 8;
                    float m = masks[r];
                    float v0 = __half2float(qkv[(size_t)r * QKVW + 1024 + cb]);
                    float v1 = __half2float(qkv[(size_t)r * QKVW + 1024 + cb + 1]);
                    float o0 = (acc[mt][nt][half * 2 + 0] + v0 * m) * m;
                    float o1 = (acc[mt][nt][half * 2 + 1] + v1 * m) * m;
                    *(float2*)(out + (size_t)r * D_ + cb) = make_float2(o0, o1);
                }
            }
        }
    } else {
        __half* Qs = smh;
        __half* Ks = smh + OFF_K;
        __half* Vt = smh + OFF_VT;
        __half* Sc = smh + OFF_SC;
        int w = tid >> 5;
        int flat = blockIdx.x - CONVBLKS;
        int qtile = flat & 3;
        int bh = flat >> 2;
        int b = bh >> 2, h = bh & 3;
        int qbase = qtile * QT2;
        int nq = T_ - qbase; if (nq > QT2) nq = QT2;
        const int qoff = h * DK_;
        const int koff = D_ + h * DK_;
        const int voff = 1024 + h * DK_;
        const float scale = 0.08838834764831845f;

#pragma unroll
        for (int u = 0; u < 4; u++) {
            int f = tid + 256 * u;
            int row = f >> 4, seg = f & 15;
            bool ok = row < nq;
            cp16(smem_u32(Qs + row * LQ + seg * 8),
                 qkv + (size_t)(b * T_ + qbase + (ok ? row : 0)) * QKVW + qoff + seg * 8, ok);
        }
        CP_COMMIT();

        int wm16 = (w & 3) * 16;
        int wk = (w >> 2) * 16;
        const uint32_t* Qw = (const uint32_t*)Qs;
        const uint32_t* Kw = (const uint32_t*)Ks;
        for (int kt = 0; kt < 7; kt++) {
            int kbase = kt * 32;
#pragma unroll
            for (int u = 0; u < 2; u++) {
                int f = tid + 256 * u;
                int row = f >> 4, seg = f & 15;
                int token = kbase + row;
                bool ok = token < T_;
                cp16(smem_u32(Ks + row * LQ + seg * 8),
                     qkv + (size_t)(b * T_ + (ok ? token : 0)) * QKVW + koff + seg * 8, ok);
            }
            CP_COMMIT();
            CP_WAIT0();
            __syncthreads();

            float acc2[2][4] = {};
#pragma unroll
            for (int ks = 0; ks < 8; ks++) {
                const uint32_t* ap = Qw + (wm16 + g) * 68 + ks * 8;
                const uint32_t* ap8 = ap + 8 * 68;
                uint32_t a0 = ap[c], a1 = ap8[c], a2 = ap[c + 4], a3 = ap8[c + 4];
#pragma unroll
                for (int nt = 0; nt < 2; nt++) {
                    const uint32_t* bp = Kw + (wk + nt * 8 + g) * 68 + ks * 8;
                    MMAH(acc2[nt], a0, a1, a2, a3, bp[c], bp[c + 4]);
                }
            }
#pragma unroll
            for (int nt = 0; nt < 2; nt++) {
#pragma unroll
                for (int hf = 0; hf < 2; hf++) {
                    int m = wm16 + g + hf * 8;
                    int tok = kbase + wk + nt * 8 + 2 * c;
                    float s0 = acc2[nt][hf * 2 + 0] * scale;
                    float s1 = acc2[nt][hf * 2 + 1] * scale;
                    bool ok0 = (tok < T_) && (masks[b * T_ + tok] > 0.f);
                    bool ok1 = (tok + 1 < T_) && (masks[b * T_ + tok + 1] > 0.f);
                    *(__half2*)(Sc + m * LSC + tok) =
                        __floats2half2_rn(ok0 ? s0 : -60000.f, ok1 ? s1 : -60000.f);
                }
            }
            __syncthreads();
        }

#pragma unroll
        for (int i = 0; i < 8; i++) {
            int row = w * 8 + i;
            __half* p = Sc + row * LSC;
            float mx = -3.4e38f;
#pragma unroll
            for (int k = lane; k < 224; k += 32) mx = fmaxf(mx, __half2float(p[k]));
#pragma unroll
            for (int o = 16; o; o >>= 1) mx = fmaxf(mx, __shfl_xor_sync(~0u, mx, o));
            float sum = 0.f;
#pragma unroll
            for (int k = lane; k < 224; k += 32) {
                float e = expf(__half2float(p[k]) - mx);
                p[k] = __float2half(e);
                sum += e;
            }
#pragma unroll
            for (int o = 16; o; o >>= 1) sum += __shfl_xor_sync(~0u, sum, o);
            float inv = 1.f / sum;
#pragma unroll
            for (int k = lane; k < 224; k += 32)
                p[k] = __float2half(__half2float(p[k]) * inv);
        }
        __syncthreads();

        int wnD = (w >> 2) * 64;
        float acc3[8][4];
#pragma unroll
        for (int j = 0; j < 8; j++)
#pragma unroll
            for (int q = 0; q < 4; q++) acc3[j][q] = 0.f;

        const uint32_t* Scw = (const uint32_t*)Sc;
        const uint32_t* Vtw = (const uint32_t*)Vt;
        for (int vt = 0; vt < 7; vt++) {
            int vbase = vt * 32;
#pragma unroll
            for (int u = 0; u < 2; u++) {
                int f = tid + 256 * u;
                int row = f >> 4, seg = f & 15;
                int token = vbase + row;
                bool ok = token < T_;
                cp16(smem_u32(Ks + row * LQ + seg * 8),
                     qkv + (size_t)(b * T_ + (ok ? token : 0)) * QKVW + voff + seg * 8, ok);
            }
            CP_COMMIT();
            CP_WAIT0();
            __syncthreads();
#pragma unroll
            for (int u = 0; u < 8; u++) {
                int idx = tid + 256 * u;
                int tp = idx & 15;
                int d  = idx >> 4;
                uint32_t lo = *(const uint16_t*)(Ks + (2 * tp) * LQ + d);
                uint32_t hi = *(const uint16_t*)(Ks + (2 * tp + 1) * LQ + d);
                *(uint32_t*)(Vt + d * LVT + 2 * tp) = lo | (hi << 16);
            }
            __syncthreads();
#pragma unroll
            for (int ks = 0; ks < 2; ks++) {
                const uint32_t* ap = Scw + (wm16 + g) * 116 + vt * 16 + ks * 8;
                const uint32_t* ap8 = ap + 8 * 116;
                uint32_t a0 = ap[c], a1 = ap8[c], a2 = ap[c + 4], a3 = ap8[c + 4];
#pragma unroll
                for (int nt = 0; nt < 8; nt++) {
                    const uint32_t* bp = Vtw + (wnD + nt * 8 + g) * 20 + ks * 8;
                    MMAH(acc3[nt], a0, a1, a2, a3, bp[c], bp[c + 4]);
                }
            }
            __syncthreads();
        }

#pragma unroll
        for (int nt = 0; nt < 8; nt++) {
            int cb = wnD + nt * 8 + 2 * c;
#pragma unroll
            for (int hf = 0; hf < 2; hf++) {
                int r = wm16 + g + hf * 8;
                if (r < nq) {
                    *(__half2*)(ctx + (size_t)(b * T_ + qbase + r) * D_ + h * DK_ + cb) =
                        __floats2half2_rn(acc3[nt][hf * 2 + 0], acc3[nt][hf * 2 + 1]);
                }
            }
        }
    }
}

// ---------------- launch ------------------------------------------------------
extern "C" void kernel_launch(void* const* d_in, const int* in_sizes, int n_in,
                              void* d_out, int out_size) {
    const float* x     = (const float*)d_in[0];
    const float* masks = (const float*)d_in[1];
    const float* ln0_w = (const float*)d_in[2];
    const float* ln0_b = (const float*)d_in[3];
    const float* ln1_w = (const float*)d_in[4];
    const float* ln1_b = (const float*)d_in[5];
    const float* qkv_w = (const float*)d_in[6];
    const float* qkv_b = (const float*)d_in[7];
    const float* out_w = (const float*)d_in[8];
    const float* out_b = (const float*)d_in[9];
    const float* fsmn_w= (const float*)d_in[10];
    const float* w1    = (const float*)d_in[11];
    const float* b1    = (const float*)d_in[12];
    const float* w2    = (const float*)d_in[13];
    const float* b2    = (const float*)d_in[14];
    float* out = (float*)d_out;

    __half *h, *qkv, *vm, *ctx, *mid, *qkv_wt, *out_wt, *w1t, *w2t;
    float *fsmn, *x1;
    cudaGetSymbolAddress((void**)&h,      g_h);
    cudaGetSymbolAddress((void**)&qkv,    g_qkv);
    cudaGetSymbolAddress((void**)&vm,     g_vm);
    cudaGetSymbolAddress((void**)&fsmn,   g_fsmn);
    cudaGetSymbolAddress((void**)&ctx,    g_ctx);
    cudaGetSymbolAddress((void**)&x1,     g_x1);
    cudaGetSymbolAddress((void**)&mid,    g_mid);
    cudaGetSymbolAddress((void**)&qkv_wt, g_qkv_wt);
    cudaGetSymbolAddress((void**)&out_wt, g_out_wt);
    cudaGetSymbolAddress((void**)&w1t,    g_w1t);
    cudaGetSymbolAddress((void**)&w2t,    g_w2t);

    cudaFuncSetAttribute(hgemm, cudaFuncAttributeMaxDynamicSharedMemorySize, DSMEM_G);
    cudaFuncSetAttribute(conv_att, cudaFuncAttributeMaxDynamicSharedMemorySize, DSMEM_CA);

    prep_kernel<<<28288, 256>>>(qkv_w, out_w, w1, w2, fsmn_w, x, ln0_w, ln0_b);

    // QKV: grid (12, 218)
    hgemm<<<dim3(QKVW / 128, R_ / 64), 256, DSMEM_G>>>(h, qkv_wt, qkv_b, nullptr, qkv,
                                                       QKVW, D_, 5, masks, nullptr, vm);

    conv_att<<<CONVBLKS + 4 * B_ * H_, 256, DSMEM_CA>>>(vm, qkv, masks, fsmn, ctx);

    // out proj: grid (4, 218)
    hgemm<<<dim3(D_ / 128, R_ / 64), 256, DSMEM_G>>>(ctx, out_wt, out_b, x1, nullptr,
                                                     D_, D_, 2, fsmn, x, nullptr);

    ln_kernel<<<R_, 128>>>(x1, ln1_w, ln1_b, h);

    // FFN1: grid (16, 218); FFN2: grid (4, 218)
    hgemm<<<dim3(2048 / 128, R_ / 64), 256, DSMEM_G>>>(h, w1t, b1, nullptr, mid,
                                                       2048, D_, 1, nullptr, nullptr, nullptr);
    hgemm<<<dim3(D_ / 128, R_ / 64), 256, DSMEM_G>>>(mid, w2t, b2, out, nullptr,
                                                     D_, 2048, 3, x1, nullptr, nullptr);
    (void)in_sizes; (void)n_in; (void)out_size;
}

// round 16
// speedup vs baseline: 1.0122x; 1.0122x over previous
#include <cuda_runtime.h>
#include <cuda_fp16.h>
#include <math.h>
#include <cstdint>

#define B_  64
#define T_  218
#define D_  512
#define R_  (B_*T_)      // 13952
#define H_  4
#define DK_ 128
#define QKVW (3*D_)      // 1536

// ---------------- scratch ----------------------------------------------------
__device__ __half g_h[R_*D_];
__device__ __half g_qkv[R_*QKVW];
__device__ __half g_vm[R_*D_];
__device__ float  g_fsmn[R_*D_];
__device__ __half g_ctx[R_*D_];
__device__ float  g_x1[R_*D_];
__device__ __half g_mid[R_*2048];
__device__ __half g_qkv_wt[QKVW*D_];
__device__ __half g_out_wt[D_*D_];
__device__ __half g_w1t[2048*D_];
__device__ __half g_w2t[D_*2048];
__device__ __half g_kwt[11*D_*D_];

// ---------------- helpers ----------------------------------------------------
__device__ __forceinline__ uint32_t smem_u32(const void* p) {
    uint32_t a;
    asm("{ .reg .u64 t; cvta.to.shared.u64 t, %1; cvt.u32.u64 %0, t; }" : "=r"(a) : "l"(p));
    return a;
}
__device__ __forceinline__ void cp16(uint32_t dst, const void* src, bool pred) {
    int sz = pred ? 16 : 0;
    asm volatile("cp.async.cg.shared.global [%0], [%1], 16, %2;"
                 :: "r"(dst), "l"(src), "r"(sz) : "memory");
}
#define CP_COMMIT() asm volatile("cp.async.commit_group;" ::: "memory")
#define CP_WAIT1()  asm volatile("cp.async.wait_group 1;" ::: "memory")
#define CP_WAIT0()  asm volatile("cp.async.wait_group 0;" ::: "memory")

#define MMAH(d, a0, a1, a2, a3, b0, b1) \
    asm volatile("mma.sync.aligned.m16n8k16.row.col.f32.f16.f16.f32 " \
                 "{%0,%1,%2,%3},{%4,%5,%6,%7},{%8,%9},{%0,%1,%2,%3};" \
                 : "+f"((d)[0]), "+f"((d)[1]), "+f"((d)[2]), "+f"((d)[3]) \
                 : "r"(a0), "r"(a1), "r"(a2), "r"(a3), "r"(b0), "r"(b1))

#define LDSM4(r0, r1, r2, r3, addr) \
    asm volatile("ldmatrix.sync.aligned.m8n8.x4.shared.b16 {%0,%1,%2,%3}, [%4];" \
                 : "=r"(r0), "=r"(r1), "=r"(r2), "=r"(r3) : "r"(addr))

#define KT  64
#define LDWH 72
#define LDWW 36
#define TILEH (128*LDWH)
#define DSMEM_BYTES (4*TILEH*2)         // 73728 B (2-stage)
#define MTSTEP (16*LDWH*2)              // 2304

// attention smem layout
#define QT2 64
#define LQ  136
#define LSC 232
#define LVT 40
#define OFF_K   (QT2*LQ)
#define OFF_VT  (OFF_K + 32*LQ)
#define OFF_SC  (OFF_VT + 128*LVT)

#define CONVBLKS 436

// ---------------- merged prep: 4 transposes + kw (coalesced) + LN0 ----------
// segments (256-thread blocks):
//  [0,768)        qkv_w; [768,1024) out_w; [1024,2048) w1; [2048,3072) w2
//  [3072,3200)    fsmn_w -> g_kwt (smem-staged, coalesced)
//  [3200,17152)   LN0
__device__ __forceinline__ void do_transpose(const float* __restrict__ src,
                                             __half* __restrict__ dst,
                                             int Kd, int Nd, int nbx, int lbid,
                                             float* tile, int tid) {
    int bx = lbid % nbx, by = lbid / nbx;
    int k0 = by * 32, n0 = bx * 32;
    int x = tid & 31, y = tid >> 5;
#pragma unroll
    for (int i = 0; i < 32; i += 8)
        tile[(y + i) * 33 + x] = src[(size_t)(k0 + y + i) * Nd + n0 + x];
    __syncthreads();
#pragma unroll
    for (int i = 0; i < 32; i += 8)
        dst[(size_t)(n0 + y + i) * Kd + k0 + x] = __float2half(tile[x * 33 + y + i]);
}

__global__ void __launch_bounds__(256)
prep_kernel(const float* __restrict__ qkv_w, const float* __restrict__ out_w,
            const float* __restrict__ w1, const float* __restrict__ w2,
            const float* __restrict__ fw,
            const float* __restrict__ x, const float* __restrict__ ln0_w,
            const float* __restrict__ ln0_b) {
    __shared__ __half sbuf[22528];               // 45056 B, overlaid uses below
    float* tile = (float*)sbuf;                  // 32*33 floats (transpose)
    float* red  = tile + 32 * 33;                // 16 floats (LN reduce)
    int bid = blockIdx.x;
    int tid = threadIdx.x;
    if (bid < 768) {
        do_transpose(qkv_w, g_qkv_wt, D_, QKVW, 48, bid, tile, tid);
    } else if (bid < 1024) {
        do_transpose(out_w, g_out_wt, D_, D_, 16, bid - 768, tile, tid);
    } else if (bid < 2048) {
        do_transpose(w1, g_w1t, D_, 2048, 64, bid - 1024, tile, tid);
    } else if (bid < 3072) {
        do_transpose(w2, g_w2t, 2048, D_, 16, bid - 2048, tile, tid);
    } else if (bid < 3200) {
        // fsmn: block handles 4 douts = 22528 contiguous floats of fw
        int blk = bid - 3072;                    // 0..127
        const float* src = fw + (size_t)blk * 22528;
        // coalesced read; stage as smem[tap*2048 + e], e = dout_local*512 + din
        for (int i = tid; i < 22528; i += 256) {
            int e = i / 11, tap = i - e * 11;
            sbuf[tap * 2048 + e] = __float2half(src[i]);
        }
        __syncthreads();
        // coalesced write: per tap, 2048 contiguous halfs at g_kwt[tap][blk*4*512]
        for (int j = tid; j < 22528; j += 256) {
            int tap = j >> 11, e = j & 2047;
            g_kwt[(size_t)tap * (D_ * D_) + (size_t)blk * 2048 + e] = sbuf[j];
        }
    } else {
        int row = bid - 3200;
        const float* xr = x + (size_t)row * D_;
        __half* orow = g_h + (size_t)row * D_;
        float v0 = xr[tid], v1 = xr[tid + 256];
        float s = v0 + v1, sq = v0 * v0 + v1 * v1;
#pragma unroll
        for (int o = 16; o; o >>= 1) {
            s  += __shfl_xor_sync(~0u, s, o);
            sq += __shfl_xor_sync(~0u, sq, o);
        }
        int lane = tid & 31, wid = tid >> 5;
        if (lane == 0) { red[wid] = s; red[8 + wid] = sq; }
        __syncthreads();
        if (tid == 0) {
            float S = 0.f, SQ = 0.f;
#pragma unroll
            for (int i = 0; i < 8; i++) { S += red[i]; SQ += red[8 + i]; }
            float mean = S * (1.f / D_);
            float var = SQ * (1.f / D_) - mean * mean;
            red[0] = mean;
            red[1] = rsqrtf(var + 1e-5f);
        }
        __syncthreads();
        float mean = red[0], inv = red[1];
        orow[tid]       = __float2half((v0 - mean) * inv * ln0_w[tid] + ln0_b[tid]);
        orow[tid + 256] = __float2half((v1 - mean) * inv * ln0_w[tid + 256] + ln0_b[tid + 256]);
    }
}

// ---------------- layer norm (half output) ----------------------------------
__global__ void ln_kernel(const float* __restrict__ x, const float* __restrict__ w,
                          const float* __restrict__ b, __half* __restrict__ out) {
    int row = blockIdx.x;
    const float* xr = x + (size_t)row * D_;
    __half* orow = out + (size_t)row * D_;
    float v[4];
    float s = 0.f, sq = 0.f;
#pragma unroll
    for (int i = 0; i < 4; i++) {
        v[i] = xr[threadIdx.x + i * 128];
        s += v[i]; sq += v[i] * v[i];
    }
    __shared__ float sm[8];
#pragma unroll
    for (int o = 16; o; o >>= 1) {
        s  += __shfl_xor_sync(~0u, s, o);
        sq += __shfl_xor_sync(~0u, sq, o);
    }
    int lane = threadIdx.x & 31, wid = threadIdx.x >> 5;
    if (lane == 0) { sm[wid] = s; sm[4 + wid] = sq; }
    __syncthreads();
    if (threadIdx.x == 0) {
        float S = sm[0] + sm[1] + sm[2] + sm[3];
        float SQ = sm[4] + sm[5] + sm[6] + sm[7];
        float mean = S * (1.f / D_);
        float var = SQ * (1.f / D_) - mean * mean;
        sm[0] = mean;
        sm[1] = rsqrtf(var + 1e-5f);
    }
    __syncthreads();
    float mean = sm[0], inv = sm[1];
#pragma unroll
    for (int i = 0; i < 4; i++) {
        int c = threadIdx.x + i * 128;
        orow[c] = __float2half((v[i] - mean) * inv * w[c] + b[c]);
    }
}

// ---------------- fp16 mma GEMM, 128x128 tile, KTILE=64, ldmatrix, 2-stage --
// epi: 0=bias->Cf; 1=bias+relu->Ch; 2=bias+add1+add2->Cf; 3=bias+add1->Cf;
//      4=bias->Ch; 5=bias->Ch(qkv) + v-cols also vm=half(v*m)
__global__ void __launch_bounds__(256)
hgemm(const __half* __restrict__ A, const __half* __restrict__ Bt,
      const float* __restrict__ bias, float* __restrict__ Cf, __half* __restrict__ Ch,
      int N, int K, int epi,
      const float* __restrict__ add1, const float* __restrict__ add2,
      __half* __restrict__ vmout) {
    extern __shared__ __half smh[];
    __half* Abuf[2] = { smh,         smh + 2 * TILEH };
    __half* Bbuf[2] = { smh + TILEH, smh + 3 * TILEH };
    int tid = threadIdx.x;
    int lane = tid & 31, wid = tid >> 5;
    int wm = (wid & 3) * 32;
    int wn = (wid >> 2) * 64;
    int g = lane >> 2, c = lane & 3;
    int rowBase = blockIdx.y * 128, colBase = blockIdx.x * 128;

    int srow[4], sseg[4];
#pragma unroll
    for (int u = 0; u < 4; u++) {
        int f = tid + 256 * u;
        srow[u] = f >> 3;
        sseg[u] = f & 7;
    }

    int laneRowA = (lane & 7) + ((lane >> 3) & 1) * 8;
    int laneKA   = (lane >> 4) * 8;
    int laneRowB = (lane & 7) + ((lane >> 4) & 1) * 8;
    int laneKB   = ((lane >> 3) & 1) * 8;
    uint32_t aOff = ((wm + laneRowA) * LDWH + laneKA) * 2;
    uint32_t bOff = ((wn + laneRowB) * LDWH + laneKB) * 2;
    uint32_t sA[2] = { smem_u32(Abuf[0]) + aOff, smem_u32(Abuf[1]) + aOff };
    uint32_t sB[2] = { smem_u32(Bbuf[0]) + bOff, smem_u32(Bbuf[1]) + bOff };

    float acc[2][8][4];
#pragma unroll
    for (int i = 0; i < 2; i++)
#pragma unroll
        for (int j = 0; j < 8; j++)
#pragma unroll
            for (int q = 0; q < 4; q++) acc[i][j][q] = 0.f;

    int nk = K >> 6;
    const __half* Arow = A + (size_t)rowBase * K;
    const __half* Brow = Bt + (size_t)colBase * K;

#pragma unroll
    for (int u = 0; u < 4; u++) {
        cp16(smem_u32(Abuf[0] + srow[u] * LDWH + sseg[u] * 8),
             Arow + (size_t)srow[u] * K + sseg[u] * 8, true);
        cp16(smem_u32(Bbuf[0] + srow[u] * LDWH + sseg[u] * 8),
             Brow + (size_t)srow[u] * K + sseg[u] * 8, true);
    }
    CP_COMMIT();

    for (int kt = 0; kt < nk; kt++) {
        int buf = kt & 1;
        if (kt + 1 < nk) {
            int nb = buf ^ 1;
            const __half* Ag = Arow + (size_t)(kt + 1) * KT;
            const __half* Bg = Brow + (size_t)(kt + 1) * KT;
#pragma unroll
            for (int u = 0; u < 4; u++) {
                cp16(smem_u32(Abuf[nb] + srow[u] * LDWH + sseg[u] * 8),
                     Ag + (size_t)srow[u] * K + sseg[u] * 8, true);
                cp16(smem_u32(Bbuf[nb] + srow[u] * LDWH + sseg[u] * 8),
                     Bg + (size_t)srow[u] * K + sseg[u] * 8, true);
            }
            CP_COMMIT();
            CP_WAIT1();
        } else {
            CP_WAIT0();
        }
        __syncthreads();
        uint32_t aB = sA[buf], bB = sB[buf];
#pragma unroll
        for (int ks = 0; ks < 4; ks++) {
            uint32_t a0r[4], a1r[4];
            LDSM4(a0r[0], a0r[1], a0r[2], a0r[3], aB + ks * 32);
            LDSM4(a1r[0], a1r[1], a1r[2], a1r[3], aB + MTSTEP + ks * 32);
#pragma unroll
            for (int np = 0; np < 4; np++) {
                uint32_t b0, b1, b2, b3;
                LDSM4(b0, b1, b2, b3, bB + np * MTSTEP + ks * 32);
                MMAH(acc[0][2 * np],     a0r[0], a0r[1], a0r[2], a0r[3], b0, b1);
                MMAH(acc[0][2 * np + 1], a0r[0], a0r[1], a0r[2], a0r[3], b2, b3);
                MMAH(acc[1][2 * np],     a1r[0], a1r[1], a1r[2], a1r[3], b0, b1);
                MMAH(acc[1][2 * np + 1], a1r[0], a1r[1], a1r[2], a1r[3], b2, b3);
            }
        }
        __syncthreads();
    }

#pragma unroll
    for (int mt = 0; mt < 2; mt++) {
#pragma unroll
        for (int nt = 0; nt < 8; nt++) {
            int cb = colBase + wn + nt * 8 + 2 * c;
            float bs0 = bias[cb], bs1 = bias[cb + 1];
#pragma unroll
            for (int half = 0; half < 2; half++) {
                int r = rowBase + wm + mt * 16 + g + half * 8;
                float v0 = acc[mt][nt][half * 2 + 0] + bs0;
                float v1 = acc[mt][nt][half * 2 + 1] + bs1;
                if (epi == 1) {
                    *(__half2*)(Ch + (size_t)r * N + cb) =
                        __floats2half2_rn(fmaxf(v0, 0.f), fmaxf(v1, 0.f));
                    continue;
                } else if (epi == 4) {
                    *(__half2*)(Ch + (size_t)r * N + cb) = __floats2half2_rn(v0, v1);
                    continue;
                } else if (epi == 5) {
                    *(__half2*)(Ch + (size_t)r * N + cb) = __floats2half2_rn(v0, v1);
                    if (cb >= 1024) {
                        float m = add1[r];
                        *(__half2*)(vmout + (size_t)r * 512 + cb - 1024) =
                            __floats2half2_rn(v0 * m, v1 * m);
                    }
                    continue;
                } else if (epi == 2) {
                    size_t id = (size_t)r * 512 + cb;
                    v0 += add1[id] + add2[id];
                    v1 += add1[id + 1] + add2[id + 1];
                } else if (epi == 3) {
                    size_t id = (size_t)r * 512 + cb;
                    v0 += add1[id];
                    v1 += add1[id + 1];
                }
                *(float2*)(Cf + (size_t)r * N + cb) = make_float2(v0, v1);
            }
        }
    }
}

// ---------------- merged conv + attention ------------------------------------
__global__ void __launch_bounds__(256, 2)
conv_att(const __half* __restrict__ vm, const __half* __restrict__ qkv,
         const float* __restrict__ masks, float* __restrict__ out,
         __half* __restrict__ ctx) {
    extern __shared__ __half smh[];
    int tid = threadIdx.x;
    int lane = tid & 31;
    int g = lane >> 2, c = lane & 3;

    if (blockIdx.x < CONVBLKS) {
        __half* Abuf[2] = { smh,         smh + 2 * TILEH };
        __half* Bbuf[2] = { smh + TILEH, smh + 3 * TILEH };
        int wid = tid >> 5;
        int wm = (wid & 3) * 32;
        int wn = (wid >> 2) * 64;
        int colBase = (blockIdx.x & 3) * 128;
        int rowBase = (blockIdx.x >> 2) * 128;

        int srow[4], sseg[4], sb[4], st[4];
#pragma unroll
        for (int u = 0; u < 4; u++) {
            int f = tid + 256 * u;
            srow[u] = f >> 3;
            sseg[u] = f & 7;
            int grow = rowBase + srow[u];
            sb[u] = grow / T_;
            st[u] = grow - sb[u] * T_;
        }

        int laneRowA = (lane & 7) + ((lane >> 3) & 1) * 8;
        int laneKA   = (lane >> 4) * 8;
        int laneRowB = (lane & 7) + ((lane >> 4) & 1) * 8;
        int laneKB   = ((lane >> 3) & 1) * 8;
        uint32_t aOff = ((wm + laneRowA) * LDWH + laneKA) * 2;
        uint32_t bOff = ((wn + laneRowB) * LDWH + laneKB) * 2;
        uint32_t sA[2] = { smem_u32(Abuf[0]) + aOff, smem_u32(Abuf[1]) + aOff };
        uint32_t sB[2] = { smem_u32(Bbuf[0]) + bOff, smem_u32(Bbuf[1]) + bOff };

        float acc[2][8][4];
#pragma unroll
        for (int i = 0; i < 2; i++)
#pragma unroll
            for (int j = 0; j < 8; j++)
#pragma unroll
                for (int q = 0; q < 4; q++) acc[i][j][q] = 0.f;

        const int NT = 11 * 8;
#pragma unroll
        for (int u = 0; u < 4; u++) {
            int src = st[u] - 5;
            bool ok = (unsigned)src < (unsigned)T_;
            cp16(smem_u32(Abuf[0] + srow[u] * LDWH + sseg[u] * 8),
                 vm + ((size_t)(sb[u] * T_ + (ok ? src : 0)) * D_ + sseg[u] * 8), ok);
            cp16(smem_u32(Bbuf[0] + srow[u] * LDWH + sseg[u] * 8),
                 g_kwt + ((size_t)(colBase + srow[u]) * D_ + sseg[u] * 8), true);
        }
        CP_COMMIT();

        for (int ti = 0; ti < NT; ti++) {
            int buf = ti & 1;
            if (ti + 1 < NT) {
                int nb = buf ^ 1;
                int tap = (ti + 1) >> 3, kt = (ti + 1) & 7;
                const __half* Bg = g_kwt + (size_t)tap * D_ * D_ + (size_t)colBase * D_ + kt * KT;
#pragma unroll
                for (int u = 0; u < 4; u++) {
                    int src = st[u] + tap - 5;
                    bool ok = (unsigned)src < (unsigned)T_;
                    cp16(smem_u32(Abuf[nb] + srow[u] * LDWH + sseg[u] * 8),
                         vm + ((size_t)(sb[u] * T_ + (ok ? src : 0)) * D_ + kt * KT + sseg[u] * 8), ok);
                    cp16(smem_u32(Bbuf[nb] + srow[u] * LDWH + sseg[u] * 8),
                         Bg + (size_t)srow[u] * D_ + sseg[u] * 8, true);
                }
                CP_COMMIT();
                CP_WAIT1();
            } else {
                CP_WAIT0();
            }
            __syncthreads();
            uint32_t aB = sA[buf], bB = sB[buf];
#pragma unroll
            for (int ks = 0; ks < 4; ks++) {
                uint32_t a0r[4], a1r[4];
                LDSM4(a0r[0], a0r[1], a0r[2], a0r[3], aB + ks * 32);
                LDSM4(a1r[0], a1r[1], a1r[2], a1r[3], aB + MTSTEP + ks * 32);
#pragma unroll
                for (int np = 0; np < 4; np++) {
                    uint32_t b0, b1, b2, b3;
                    LDSM4(b0, b1, b2, b3, bB + np * MTSTEP + ks * 32);
                    MMAH(acc[0][2 * np],     a0r[0], a0r[1], a0r[2], a0r[3], b0, b1);
                    MMAH(acc[0][2 * np + 1], a0r[0], a0r[1], a0r[2], a0r[3], b2, b3);
                    MMAH(acc[1][2 * np],     a1r[0], a1r[1], a1r[2], a1r[3], b0, b1);
                    MMAH(acc[1][2 * np + 1], a1r[0], a1r[1], a1r[2], a1r[3], b2, b3);
                }
            }
            __syncthreads();
        }

#pragma unroll
        for (int mt = 0; mt < 2; mt++) {
#pragma unroll
            for (int nt = 0; nt < 8; nt++) {
                int cb = colBase + wn + nt * 8 + 2 * c;
#pragma unroll
                for (int half = 0; half < 2; half++) {
                    int r = rowBase + wm + mt * 16 + g + half * 8;
                    float m = masks[r];
                    float v0 = __half2float(qkv[(size_t)r * QKVW + 1024 + cb]);
                    float v1 = __half2float(qkv[(size_t)r * QKVW + 1024 + cb + 1]);
                    float o0 = (acc[mt][nt][half * 2 + 0] + v0 * m) * m;
                    float o1 = (acc[mt][nt][half * 2 + 1] + v1 * m) * m;
                    *(float2*)(out + (size_t)r * D_ + cb) = make_float2(o0, o1);
                }
            }
        }
    } else {
        __half* Qs = smh;
        __half* Ks = smh + OFF_K;
        __half* Vt = smh + OFF_VT;
        __half* Sc = smh + OFF_SC;
        int w = tid >> 5;
        int flat = blockIdx.x - CONVBLKS;
        int qtile = flat & 3;
        int bh = flat >> 2;
        int b = bh >> 2, h = bh & 3;
        int qbase = qtile * QT2;
        int nq = T_ - qbase; if (nq > QT2) nq = QT2;
        const int qoff = h * DK_;
        const int koff = D_ + h * DK_;
        const int voff = 1024 + h * DK_;
        const float scale = 0.08838834764831845f;

#pragma unroll
        for (int u = 0; u < 4; u++) {
            int f = tid + 256 * u;
            int row = f >> 4, seg = f & 15;
            bool ok = row < nq;
            cp16(smem_u32(Qs + row * LQ + seg * 8),
                 qkv + (size_t)(b * T_ + qbase + (ok ? row : 0)) * QKVW + qoff + seg * 8, ok);
        }
        CP_COMMIT();

        int wm16 = (w & 3) * 16;
        int wk = (w >> 2) * 16;
        const uint32_t* Qw = (const uint32_t*)Qs;
        const uint32_t* Kw = (const uint32_t*)Ks;
        for (int kt = 0; kt < 7; kt++) {
            int kbase = kt * 32;
#pragma unroll
            for (int u = 0; u < 2; u++) {
                int f = tid + 256 * u;
                int row = f >> 4, seg = f & 15;
                int token = kbase + row;
                bool ok = token < T_;
                cp16(smem_u32(Ks + row * LQ + seg * 8),
                     qkv + (size_t)(b * T_ + (ok ? token : 0)) * QKVW + koff + seg * 8, ok);
            }
            CP_COMMIT();
            CP_WAIT0();
            __syncthreads();

            float acc2[2][4] = {};
#pragma unroll
            for (int ks = 0; ks < 8; ks++) {
                const uint32_t* ap = Qw + (wm16 + g) * 68 + ks * 8;
                const uint32_t* ap8 = ap + 8 * 68;
                uint32_t a0 = ap[c], a1 = ap8[c], a2 = ap[c + 4], a3 = ap8[c + 4];
#pragma unroll
                for (int nt = 0; nt < 2; nt++) {
                    const uint32_t* bp = Kw + (wk + nt * 8 + g) * 68 + ks * 8;
                    MMAH(acc2[nt], a0, a1, a2, a3, bp[c], bp[c + 4]);
                }
            }
#pragma unroll
            for (int nt = 0; nt < 2; nt++) {
#pragma unroll
                for (int hf = 0; hf < 2; hf++) {
                    int m = wm16 + g + hf * 8;
                    int tok = kbase + wk + nt * 8 + 2 * c;
                    float s0 = acc2[nt][hf * 2 + 0] * scale;
                    float s1 = acc2[nt][hf * 2 + 1] * scale;
                    bool ok0 = (tok < T_) && (masks[b * T_ + tok] > 0.f);
                    bool ok1 = (tok + 1 < T_) && (masks[b * T_ + tok + 1] > 0.f);
                    *(__half2*)(Sc + m * LSC + tok) =
                        __floats2half2_rn(ok0 ? s0 : -60000.f, ok1 ? s1 : -60000.f);
                }
            }
            __syncthreads();
        }

#pragma unroll
        for (int i = 0; i < 8; i++) {
            int row = w * 8 + i;
            __half* p = Sc + row * LSC;
            float mx = -3.4e38f;
#pragma unroll
            for (int k = lane; k < 224; k += 32) mx = fmaxf(mx, __half2float(p[k]));
#pragma unroll
            for (int o = 16; o; o >>= 1) mx = fmaxf(mx, __shfl_xor_sync(~0u, mx, o));
            float sum = 0.f;
#pragma unroll
            for (int k = lane; k < 224; k += 32) {
                float e = expf(__half2float(p[k]) - mx);
                p[k] = __float2half(e);
                sum += e;
            }
#pragma unroll
            for (int o = 16; o; o >>= 1) sum += __shfl_xor_sync(~0u, sum, o);
            float inv = 1.f / sum;
#pragma unroll
            for (int k = lane; k < 224; k += 32)
                p[k] = __float2half(__half2float(p[k]) * inv);
        }
        __syncthreads();

        int wnD = (w >> 2) * 64;
        float acc3[8][4];
#pragma unroll
        for (int j = 0; j < 8; j++)
#pragma unroll
            for (int q = 0; q < 4; q++) acc3[j][q] = 0.f;

        const uint32_t* Scw = (const uint32_t*)Sc;
        const uint32_t* Vtw = (const uint32_t*)Vt;
        for (int vt = 0; vt < 7; vt++) {
            int vbase = vt * 32;
#pragma unroll
            for (int u = 0; u < 2; u++) {
                int f = tid + 256 * u;
                int row = f >> 4, seg = f & 15;
                int token = vbase + row;
                bool ok = token < T_;
                cp16(smem_u32(Ks + row * LQ + seg * 8),
                     qkv + (size_t)(b * T_ + (ok ? token : 0)) * QKVW + voff + seg * 8, ok);
            }
            CP_COMMIT();
            CP_WAIT0();
            __syncthreads();
#pragma unroll
            for (int u = 0; u < 8; u++) {
                int idx = tid + 256 * u;
                int tp = idx & 15;
                int d  = idx >> 4;
                uint32_t lo = *(const uint16_t*)(Ks + (2 * tp) * LQ + d);
                uint32_t hi = *(const uint16_t*)(Ks + (2 * tp + 1) * LQ + d);
                *(uint32_t*)(Vt + d * LVT + 2 * tp) = lo | (hi << 16);
            }
            __syncthreads();
#pragma unroll
            for (int ks = 0; ks < 2; ks++) {
                const uint32_t* ap = Scw + (wm16 + g) * 116 + vt * 16 + ks * 8;
                const uint32_t* ap8 = ap + 8 * 116;
                uint32_t a0 = ap[c], a1 = ap8[c], a2 = ap[c + 4], a3 = ap8[c + 4];
#pragma unroll
                for (int nt = 0; nt < 8; nt++) {
                    const uint32_t* bp = Vtw + (wnD + nt * 8 + g) * 20 + ks * 8;
                    MMAH(acc3[nt], a0, a1, a2, a3, bp[c], bp[c + 4]);
                }
            }
            __syncthreads();
        }

#pragma unroll
        for (int nt = 0; nt < 8; nt++) {
            int cb = wnD + nt * 8 + 2 * c;
#pragma unroll
            for (int hf = 0; hf < 2; hf++) {
                int r = wm16 + g + hf * 8;
                if (r < nq) {
                    *(__half2*)(ctx + (size_t)(b * T_ + qbase + r) * D_ + h * DK_ + cb) =
                        __floats2half2_rn(acc3[nt][hf * 2 + 0], acc3[nt][hf * 2 + 1]);
                }
            }
        }
    }
}

// ---------------- launch ------------------------------------------------------
extern "C" void kernel_launch(void* const* d_in, const int* in_sizes, int n_in,
                              void* d_out, int out_size) {
    const float* x     = (const float*)d_in[0];
    const float* masks = (const float*)d_in[1];
    const float* ln0_w = (const float*)d_in[2];
    const float* ln0_b = (const float*)d_in[3];
    const float* ln1_w = (const float*)d_in[4];
    const float* ln1_b = (const float*)d_in[5];
    const float* qkv_w = (const float*)d_in[6];
    const float* qkv_b = (const float*)d_in[7];
    const float* out_w = (const float*)d_in[8];
    const float* out_b = (const float*)d_in[9];
    const float* fsmn_w= (const float*)d_in[10];
    const float* w1    = (const float*)d_in[11];
    const float* b1    = (const float*)d_in[12];
    const float* w2    = (const float*)d_in[13];
    const float* b2    = (const float*)d_in[14];
    float* out = (float*)d_out;

    __half *h, *qkv, *vm, *ctx, *mid, *qkv_wt, *out_wt, *w1t, *w2t;
    float *fsmn, *x1;
    cudaGetSymbolAddress((void**)&h,      g_h);
    cudaGetSymbolAddress((void**)&qkv,    g_qkv);
    cudaGetSymbolAddress((void**)&vm,     g_vm);
    cudaGetSymbolAddress((void**)&fsmn,   g_fsmn);
    cudaGetSymbolAddress((void**)&ctx,    g_ctx);
    cudaGetSymbolAddress((void**)&x1,     g_x1);
    cudaGetSymbolAddress((void**)&mid,    g_mid);
    cudaGetSymbolAddress((void**)&qkv_wt, g_qkv_wt);
    cudaGetSymbolAddress((void**)&out_wt, g_out_wt);
    cudaGetSymbolAddress((void**)&w1t,    g_w1t);
    cudaGetSymbolAddress((void**)&w2t,    g_w2t);

    cudaFuncSetAttribute(hgemm, cudaFuncAttributeMaxDynamicSharedMemorySize, DSMEM_BYTES);
    cudaFuncSetAttribute(conv_att, cudaFuncAttributeMaxDynamicSharedMemorySize, DSMEM_BYTES);

    prep_kernel<<<17152, 256>>>(qkv_w, out_w, w1, w2, fsmn_w, x, ln0_w, ln0_b);

    hgemm<<<dim3(QKVW / 128, R_ / 128), 256, DSMEM_BYTES>>>(h, qkv_wt, qkv_b, nullptr, qkv,
                                                            QKVW, D_, 5, masks, nullptr, vm);

    conv_att<<<CONVBLKS + 4 * B_ * H_, 256, DSMEM_BYTES>>>(vm, qkv, masks, fsmn, ctx);

    hgemm<<<dim3(D_ / 128, R_ / 128), 256, DSMEM_BYTES>>>(ctx, out_wt, out_b, x1, nullptr,
                                                          D_, D_, 2, fsmn, x, nullptr);

    ln_kernel<<<R_, 128>>>(x1, ln1_w, ln1_b, h);

    hgemm<<<dim3(2048 / 128, R_ / 128), 256, DSMEM_BYTES>>>(h, w1t, b1, nullptr, mid,
                                                            2048, D_, 1, nullptr, nullptr, nullptr);
    hgemm<<<dim3(D_ / 128, R_ / 128), 256, DSMEM_BYTES>>>(mid, w2t, b2, out, nullptr,
                                                          D_, 2048, 3, x1, nullptr, nullptr);
    (void)in_sizes; (void)n_in; (void)out_size;
}

// round 17
// speedup vs baseline: 1.0212x; 1.0089x over previous
#include <cuda_runtime.h>
#include <cuda_fp16.h>
#include <math.h>
#include <cstdint>

#define B_  64
#define T_  218
#define D_  512
#define R_  (B_*T_)      // 13952
#define H_  4
#define DK_ 128
#define QKVW (3*D_)      // 1536

// ---------------- scratch ----------------------------------------------------
__device__ __half g_h[R_*D_];
__device__ __half g_qkv[R_*QKVW];
__device__ __half g_vm[R_*D_];
__device__ __half g_fsmn[R_*D_];              // now half
__device__ __half g_ctx[R_*D_];
__device__ float  g_x1[R_*D_];
__device__ __half g_mid[R_*2048];
__device__ __half g_qkv_wt[QKVW*D_];
__device__ __half g_out_wt[D_*D_];
__device__ __half g_w1t[2048*D_];
__device__ __half g_w2t[D_*2048];
__device__ __half g_kwt[11*D_*D_];

// ---------------- helpers ----------------------------------------------------
__device__ __forceinline__ uint32_t smem_u32(const void* p) {
    uint32_t a;
    asm("{ .reg .u64 t; cvta.to.shared.u64 t, %1; cvt.u32.u64 %0, t; }" : "=r"(a) : "l"(p));
    return a;
}
__device__ __forceinline__ void cp16(uint32_t dst, const void* src, bool pred) {
    int sz = pred ? 16 : 0;
    asm volatile("cp.async.cg.shared.global [%0], [%1], 16, %2;"
                 :: "r"(dst), "l"(src), "r"(sz) : "memory");
}
#define CP_COMMIT() asm volatile("cp.async.commit_group;" ::: "memory")
#define CP_WAIT1()  asm volatile("cp.async.wait_group 1;" ::: "memory")
#define CP_WAIT0()  asm volatile("cp.async.wait_group 0;" ::: "memory")

#define MMAH(d, a0, a1, a2, a3, b0, b1) \
    asm volatile("mma.sync.aligned.m16n8k16.row.col.f32.f16.f16.f32 " \
                 "{%0,%1,%2,%3},{%4,%5,%6,%7},{%8,%9},{%0,%1,%2,%3};" \
                 : "+f"((d)[0]), "+f"((d)[1]), "+f"((d)[2]), "+f"((d)[3]) \
                 : "r"(a0), "r"(a1), "r"(a2), "r"(a3), "r"(b0), "r"(b1))

#define LDSM4(r0, r1, r2, r3, addr) \
    asm volatile("ldmatrix.sync.aligned.m8n8.x4.shared.b16 {%0,%1,%2,%3}, [%4];" \
                 : "=r"(r0), "=r"(r1), "=r"(r2), "=r"(r3) : "r"(addr))

#define KT  64
#define LDWH 72
#define TILEH (128*LDWH)
#define DSMEM_BYTES (4*TILEH*2)         // 73728 B (2-stage)
#define MTSTEP (16*LDWH*2)              // 2304

// attention smem layout
#define QT2 64
#define LQ  136
#define LSC 232
#define LVT 40
#define OFF_K   (QT2*LQ)
#define OFF_VT  (OFF_K + 32*LQ)
#define OFF_SC  (OFF_VT + 128*LVT)

#define CONVBLKS 436

// ---------------- warp-per-row layer norm helper -----------------------------
__device__ __forceinline__ void ln_row_warp(const float* __restrict__ xr,
                                            const float* __restrict__ w,
                                            const float* __restrict__ b,
                                            __half* __restrict__ orow, int lane) {
    float v[16];
    float s = 0.f, sq = 0.f;
#pragma unroll
    for (int i = 0; i < 16; i++) {
        v[i] = xr[lane + i * 32];
        s += v[i]; sq += v[i] * v[i];
    }
#pragma unroll
    for (int o = 16; o; o >>= 1) {
        s  += __shfl_xor_sync(~0u, s, o);
        sq += __shfl_xor_sync(~0u, sq, o);
    }
    float mean = s * (1.f / D_);
    float var = sq * (1.f / D_) - mean * mean;
    float inv = rsqrtf(var + 1e-5f);
#pragma unroll
    for (int i = 0; i < 16; i++) {
        int cc = lane + i * 32;
        orow[cc] = __float2half((v[i] - mean) * inv * w[cc] + b[cc]);
    }
}

// ---------------- merged prep: 4 transposes + kw (coalesced) + LN0 ----------
// [0,768) qkv_w; [768,1024) out_w; [1024,2048) w1; [2048,3072) w2;
// [3072,3200) fsmn; [3200,4944) LN0 (8 rows/block, warp-per-row)
__device__ __forceinline__ void do_transpose(const float* __restrict__ src,
                                             __half* __restrict__ dst,
                                             int Kd, int Nd, int nbx, int lbid,
                                             float* tile, int tid) {
    int bx = lbid % nbx, by = lbid / nbx;
    int k0 = by * 32, n0 = bx * 32;
    int x = tid & 31, y = tid >> 5;
#pragma unroll
    for (int i = 0; i < 32; i += 8)
        tile[(y + i) * 33 + x] = src[(size_t)(k0 + y + i) * Nd + n0 + x];
    __syncthreads();
#pragma unroll
    for (int i = 0; i < 32; i += 8)
        dst[(size_t)(n0 + y + i) * Kd + k0 + x] = __float2half(tile[x * 33 + y + i]);
}

__global__ void __launch_bounds__(256)
prep_kernel(const float* __restrict__ qkv_w, const float* __restrict__ out_w,
            const float* __restrict__ w1, const float* __restrict__ w2,
            const float* __restrict__ fw,
            const float* __restrict__ x, const float* __restrict__ ln0_w,
            const float* __restrict__ ln0_b) {
    __shared__ __half sbuf[22528];
    float* tile = (float*)sbuf;
    int bid = blockIdx.x;
    int tid = threadIdx.x;
    if (bid < 768) {
        do_transpose(qkv_w, g_qkv_wt, D_, QKVW, 48, bid, tile, tid);
    } else if (bid < 1024) {
        do_transpose(out_w, g_out_wt, D_, D_, 16, bid - 768, tile, tid);
    } else if (bid < 2048) {
        do_transpose(w1, g_w1t, D_, 2048, 64, bid - 1024, tile, tid);
    } else if (bid < 3072) {
        do_transpose(w2, g_w2t, 2048, D_, 16, bid - 2048, tile, tid);
    } else if (bid < 3200) {
        int blk = bid - 3072;
        const float* src = fw + (size_t)blk * 22528;
        for (int i = tid; i < 22528; i += 256) {
            int e = i / 11, tap = i - e * 11;
            sbuf[tap * 2048 + e] = __float2half(src[i]);
        }
        __syncthreads();
        for (int j = tid; j < 22528; j += 256) {
            int tap = j >> 11, e = j & 2047;
            g_kwt[(size_t)tap * (D_ * D_) + (size_t)blk * 2048 + e] = sbuf[j];
        }
    } else {
        // LN0: 8 rows per block, warp per row (no block sync)
        int lane = tid & 31, wrp = tid >> 5;
        int row = (bid - 3200) * 8 + wrp;
        ln_row_warp(x + (size_t)row * D_, ln0_w, ln0_b, g_h + (size_t)row * D_, lane);
    }
}

// ---------------- LN1: warp-per-row, 8 rows/block -----------------------------
__global__ void __launch_bounds__(256)
ln_kernel(const float* __restrict__ x, const float* __restrict__ w,
          const float* __restrict__ b, __half* __restrict__ out) {
    int lane = threadIdx.x & 31, wrp = threadIdx.x >> 5;
    int row = blockIdx.x * 8 + wrp;
    ln_row_warp(x + (size_t)row * D_, w, b, out + (size_t)row * D_, lane);
}

// ---------------- fp16 mma GEMM, 128x128 tile, KTILE=64, ldmatrix, 2-stage --
// epi: 0=bias->Cf; 1=bias+relu->Ch; 2=bias+half(add1h)+add2->Cf; 3=bias+add1->Cf;
//      4=bias->Ch; 5=bias->Ch(qkv) + v-cols also vm=half(v*m)
__global__ void __launch_bounds__(256)
hgemm(const __half* __restrict__ A, const __half* __restrict__ Bt,
      const float* __restrict__ bias, float* __restrict__ Cf, __half* __restrict__ Ch,
      int N, int K, int epi,
      const float* __restrict__ add1, const float* __restrict__ add2,
      __half* __restrict__ vmout) {
    extern __shared__ __half smh[];
    __half* Abuf[2] = { smh,         smh + 2 * TILEH };
    __half* Bbuf[2] = { smh + TILEH, smh + 3 * TILEH };
    int tid = threadIdx.x;
    int lane = tid & 31, wid = tid >> 5;
    int wm = (wid & 3) * 32;
    int wn = (wid >> 2) * 64;
    int g = lane >> 2, c = lane & 3;
    int rowBase = blockIdx.y * 128, colBase = blockIdx.x * 128;

    int srow[4], sseg[4];
#pragma unroll
    for (int u = 0; u < 4; u++) {
        int f = tid + 256 * u;
        srow[u] = f >> 3;
        sseg[u] = f & 7;
    }

    int laneRowA = (lane & 7) + ((lane >> 3) & 1) * 8;
    int laneKA   = (lane >> 4) * 8;
    int laneRowB = (lane & 7) + ((lane >> 4) & 1) * 8;
    int laneKB   = ((lane >> 3) & 1) * 8;
    uint32_t aOff = ((wm + laneRowA) * LDWH + laneKA) * 2;
    uint32_t bOff = ((wn + laneRowB) * LDWH + laneKB) * 2;
    uint32_t sA[2] = { smem_u32(Abuf[0]) + aOff, smem_u32(Abuf[1]) + aOff };
    uint32_t sB[2] = { smem_u32(Bbuf[0]) + bOff, smem_u32(Bbuf[1]) + bOff };

    float acc[2][8][4];
#pragma unroll
    for (int i = 0; i < 2; i++)
#pragma unroll
        for (int j = 0; j < 8; j++)
#pragma unroll
            for (int q = 0; q < 4; q++) acc[i][j][q] = 0.f;

    int nk = K >> 6;
    const __half* Arow = A + (size_t)rowBase * K;
    const __half* Brow = Bt + (size_t)colBase * K;

#pragma unroll
    for (int u = 0; u < 4; u++) {
        cp16(smem_u32(Abuf[0] + srow[u] * LDWH + sseg[u] * 8),
             Arow + (size_t)srow[u] * K + sseg[u] * 8, true);
        cp16(smem_u32(Bbuf[0] + srow[u] * LDWH + sseg[u] * 8),
             Brow + (size_t)srow[u] * K + sseg[u] * 8, true);
    }
    CP_COMMIT();

    for (int kt = 0; kt < nk; kt++) {
        int buf = kt & 1;
        if (kt + 1 < nk) {
            int nb = buf ^ 1;
            const __half* Ag = Arow + (size_t)(kt + 1) * KT;
            const __half* Bg = Brow + (size_t)(kt + 1) * KT;
#pragma unroll
            for (int u = 0; u < 4; u++) {
                cp16(smem_u32(Abuf[nb] + srow[u] * LDWH + sseg[u] * 8),
                     Ag + (size_t)srow[u] * K + sseg[u] * 8, true);
                cp16(smem_u32(Bbuf[nb] + srow[u] * LDWH + sseg[u] * 8),
                     Bg + (size_t)srow[u] * K + sseg[u] * 8, true);
            }
            CP_COMMIT();
            CP_WAIT1();
        } else {
            CP_WAIT0();
        }
        __syncthreads();
        uint32_t aB = sA[buf], bB = sB[buf];
#pragma unroll
        for (int ks = 0; ks < 4; ks++) {
            uint32_t a0r[4], a1r[4];
            LDSM4(a0r[0], a0r[1], a0r[2], a0r[3], aB + ks * 32);
            LDSM4(a1r[0], a1r[1], a1r[2], a1r[3], aB + MTSTEP + ks * 32);
#pragma unroll
            for (int np = 0; np < 4; np++) {
                uint32_t b0, b1, b2, b3;
                LDSM4(b0, b1, b2, b3, bB + np * MTSTEP + ks * 32);
                MMAH(acc[0][2 * np],     a0r[0], a0r[1], a0r[2], a0r[3], b0, b1);
                MMAH(acc[0][2 * np + 1], a0r[0], a0r[1], a0r[2], a0r[3], b2, b3);
                MMAH(acc[1][2 * np],     a1r[0], a1r[1], a1r[2], a1r[3], b0, b1);
                MMAH(acc[1][2 * np + 1], a1r[0], a1r[1], a1r[2], a1r[3], b2, b3);
            }
        }
        __syncthreads();
    }

#pragma unroll
    for (int mt = 0; mt < 2; mt++) {
#pragma unroll
        for (int nt = 0; nt < 8; nt++) {
            int cb = colBase + wn + nt * 8 + 2 * c;
            float bs0 = bias[cb], bs1 = bias[cb + 1];
#pragma unroll
            for (int half = 0; half < 2; half++) {
                int r = rowBase + wm + mt * 16 + g + half * 8;
                float v0 = acc[mt][nt][half * 2 + 0] + bs0;
                float v1 = acc[mt][nt][half * 2 + 1] + bs1;
                if (epi == 1) {
                    *(__half2*)(Ch + (size_t)r * N + cb) =
                        __floats2half2_rn(fmaxf(v0, 0.f), fmaxf(v1, 0.f));
                    continue;
                } else if (epi == 4) {
                    *(__half2*)(Ch + (size_t)r * N + cb) = __floats2half2_rn(v0, v1);
                    continue;
                } else if (epi == 5) {
                    *(__half2*)(Ch + (size_t)r * N + cb) = __floats2half2_rn(v0, v1);
                    if (cb >= 1024) {
                        float m = add1[r];
                        *(__half2*)(vmout + (size_t)r * 512 + cb - 1024) =
                            __floats2half2_rn(v0 * m, v1 * m);
                    }
                    continue;
                } else if (epi == 2) {
                    size_t id = (size_t)r * 512 + cb;
                    const __half* f = (const __half*)add1;
                    v0 += __half2float(f[id]) + add2[id];
                    v1 += __half2float(f[id + 1]) + add2[id + 1];
                } else if (epi == 3) {
                    size_t id = (size_t)r * 512 + cb;
                    v0 += add1[id];
                    v1 += add1[id + 1];
                }
                *(float2*)(Cf + (size_t)r * N + cb) = make_float2(v0, v1);
            }
        }
    }
}

// ---------------- merged conv + attention ------------------------------------
__global__ void __launch_bounds__(256, 2)
conv_att(const __half* __restrict__ vm, const __half* __restrict__ qkv,
         const float* __restrict__ masks, __half* __restrict__ out,
         __half* __restrict__ ctx) {
    extern __shared__ __half smh[];
    int tid = threadIdx.x;
    int lane = tid & 31;
    int g = lane >> 2, c = lane & 3;

    if (blockIdx.x < CONVBLKS) {
        __half* Abuf[2] = { smh,         smh + 2 * TILEH };
        __half* Bbuf[2] = { smh + TILEH, smh + 3 * TILEH };
        int wid = tid >> 5;
        int wm = (wid & 3) * 32;
        int wn = (wid >> 2) * 64;
        int colBase = (blockIdx.x & 3) * 128;
        int rowBase = (blockIdx.x >> 2) * 128;

        int srow[4], sseg[4], sb[4], st[4];
#pragma unroll
        for (int u = 0; u < 4; u++) {
            int f = tid + 256 * u;
            srow[u] = f >> 3;
            sseg[u] = f & 7;
            int grow = rowBase + srow[u];
            sb[u] = grow / T_;
            st[u] = grow - sb[u] * T_;
        }

        int laneRowA = (lane & 7) + ((lane >> 3) & 1) * 8;
        int laneKA   = (lane >> 4) * 8;
        int laneRowB = (lane & 7) + ((lane >> 4) & 1) * 8;
        int laneKB   = ((lane >> 3) & 1) * 8;
        uint32_t aOff = ((wm + laneRowA) * LDWH + laneKA) * 2;
        uint32_t bOff = ((wn + laneRowB) * LDWH + laneKB) * 2;
        uint32_t sA[2] = { smem_u32(Abuf[0]) + aOff, smem_u32(Abuf[1]) + aOff };
        uint32_t sB[2] = { smem_u32(Bbuf[0]) + bOff, smem_u32(Bbuf[1]) + bOff };

        float acc[2][8][4];
#pragma unroll
        for (int i = 0; i < 2; i++)
#pragma unroll
            for (int j = 0; j < 8; j++)
#pragma unroll
                for (int q = 0; q < 4; q++) acc[i][j][q] = 0.f;

        const int NT = 11 * 8;
#pragma unroll
        for (int u = 0; u < 4; u++) {
            int src = st[u] - 5;
            bool ok = (unsigned)src < (unsigned)T_;
            cp16(smem_u32(Abuf[0] + srow[u] * LDWH + sseg[u] * 8),
                 vm + ((size_t)(sb[u] * T_ + (ok ? src : 0)) * D_ + sseg[u] * 8), ok);
            cp16(smem_u32(Bbuf[0] + srow[u] * LDWH + sseg[u] * 8),
                 g_kwt + ((size_t)(colBase + srow[u]) * D_ + sseg[u] * 8), true);
        }
        CP_COMMIT();

        for (int ti = 0; ti < NT; ti++) {
            int buf = ti & 1;
            if (ti + 1 < NT) {
                int nb = buf ^ 1;
                int tap = (ti + 1) >> 3, kt = (ti + 1) & 7;
                const __half* Bg = g_kwt + (size_t)tap * D_ * D_ + (size_t)colBase * D_ + kt * KT;
#pragma unroll
                for (int u = 0; u < 4; u++) {
                    int src = st[u] + tap - 5;
                    bool ok = (unsigned)src < (unsigned)T_;
                    cp16(smem_u32(Abuf[nb] + srow[u] * LDWH + sseg[u] * 8),
                         vm + ((size_t)(sb[u] * T_ + (ok ? src : 0)) * D_ + kt * KT + sseg[u] * 8), ok);
                    cp16(smem_u32(Bbuf[nb] + srow[u] * LDWH + sseg[u] * 8),
                         Bg + (size_t)srow[u] * D_ + sseg[u] * 8, true);
                }
                CP_COMMIT();
                CP_WAIT1();
            } else {
                CP_WAIT0();
            }
            __syncthreads();
            uint32_t aB = sA[buf], bB = sB[buf];
#pragma unroll
            for (int ks = 0; ks < 4; ks++) {
                uint32_t a0r[4], a1r[4];
                LDSM4(a0r[0], a0r[1], a0r[2], a0r[3], aB + ks * 32);
                LDSM4(a1r[0], a1r[1], a1r[2], a1r[3], aB + MTSTEP + ks * 32);
#pragma unroll
                for (int np = 0; np < 4; np++) {
                    uint32_t b0, b1, b2, b3;
                    LDSM4(b0, b1, b2, b3, bB + np * MTSTEP + ks * 32);
                    MMAH(acc[0][2 * np],     a0r[0], a0r[1], a0r[2], a0r[3], b0, b1);
                    MMAH(acc[0][2 * np + 1], a0r[0], a0r[1], a0r[2], a0r[3], b2, b3);
                    MMAH(acc[1][2 * np],     a1r[0], a1r[1], a1r[2], a1r[3], b0, b1);
                    MMAH(acc[1][2 * np + 1], a1r[0], a1r[1], a1r[2], a1r[3], b2, b3);
                }
            }
            __syncthreads();
        }

#pragma unroll
        for (int mt = 0; mt < 2; mt++) {
#pragma unroll
            for (int nt = 0; nt < 8; nt++) {
                int cb = colBase + wn + nt * 8 + 2 * c;
#pragma unroll
                for (int half = 0; half < 2; half++) {
                    int r = rowBase + wm + mt * 16 + g + half * 8;
                    float m = masks[r];
                    float v0 = __half2float(qkv[(size_t)r * QKVW + 1024 + cb]);
                    float v1 = __half2float(qkv[(size_t)r * QKVW + 1024 + cb + 1]);
                    float o0 = (acc[mt][nt][half * 2 + 0] + v0 * m) * m;
                    float o1 = (acc[mt][nt][half * 2 + 1] + v1 * m) * m;
                    *(__half2*)(out + (size_t)r * D_ + cb) = __floats2half2_rn(o0, o1);
                }
            }
        }
    } else {
        __half* Qs = smh;
        __half* Ks = smh + OFF_K;
        __half* Vt = smh + OFF_VT;
        __half* Sc = smh + OFF_SC;
        int w = tid >> 5;
        int flat = blockIdx.x - CONVBLKS;
        int qtile = flat & 3;
        int bh = flat >> 2;
        int b = bh >> 2, h = bh & 3;
        int qbase = qtile * QT2;
        int nq = T_ - qbase; if (nq > QT2) nq = QT2;
        const int qoff = h * DK_;
        const int koff = D_ + h * DK_;
        const int voff = 1024 + h * DK_;
        const float scale = 0.08838834764831845f;

#pragma unroll
        for (int u = 0; u < 4; u++) {
            int f = tid + 256 * u;
            int row = f >> 4, seg = f & 15;
            bool ok = row < nq;
            cp16(smem_u32(Qs + row * LQ + seg * 8),
                 qkv + (size_t)(b * T_ + qbase + (ok ? row : 0)) * QKVW + qoff + seg * 8, ok);
        }
        CP_COMMIT();

        int wm16 = (w & 3) * 16;
        int wk = (w >> 2) * 16;
        const uint32_t* Qw = (const uint32_t*)Qs;
        const uint32_t* Kw = (const uint32_t*)Ks;
        for (int kt = 0; kt < 7; kt++) {
            int kbase = kt * 32;
#pragma unroll
            for (int u = 0; u < 2; u++) {
                int f = tid + 256 * u;
                int row = f >> 4, seg = f & 15;
                int token = kbase + row;
                bool ok = token < T_;
                cp16(smem_u32(Ks + row * LQ + seg * 8),
                     qkv + (size_t)(b * T_ + (ok ? token : 0)) * QKVW + koff + seg * 8, ok);
            }
            CP_COMMIT();
            CP_WAIT0();
            __syncthreads();

            float acc2[2][4] = {};
#pragma unroll
            for (int ks = 0; ks < 8; ks++) {
                const uint32_t* ap = Qw + (wm16 + g) * 68 + ks * 8;
                const uint32_t* ap8 = ap + 8 * 68;
                uint32_t a0 = ap[c], a1 = ap8[c], a2 = ap[c + 4], a3 = ap8[c + 4];
#pragma unroll
                for (int nt = 0; nt < 2; nt++) {
                    const uint32_t* bp = Kw + (wk + nt * 8 + g) * 68 + ks * 8;
                    MMAH(acc2[nt], a0, a1, a2, a3, bp[c], bp[c + 4]);
                }
            }
#pragma unroll
            for (int nt = 0; nt < 2; nt++) {
#pragma unroll
                for (int hf = 0; hf < 2; hf++) {
                    int m = wm16 + g + hf * 8;
                    int tok = kbase + wk + nt * 8 + 2 * c;
                    float s0 = acc2[nt][hf * 2 + 0] * scale;
                    float s1 = acc2[nt][hf * 2 + 1] * scale;
                    bool ok0 = (tok < T_) && (masks[b * T_ + tok] > 0.f);
                    bool ok1 = (tok + 1 < T_) && (masks[b * T_ + tok + 1] > 0.f);
                    *(__half2*)(Sc + m * LSC + tok) =
                        __floats2half2_rn(ok0 ? s0 : -60000.f, ok1 ? s1 : -60000.f);
                }
            }
            __syncthreads();
        }

#pragma unroll
        for (int i = 0; i < 8; i++) {
            int row = w * 8 + i;
            __half* p = Sc + row * LSC;
            float mx = -3.4e38f;
#pragma unroll
            for (int k = lane; k < 224; k += 32) mx = fmaxf(mx, __half2float(p[k]));
#pragma unroll
            for (int o = 16; o; o >>= 1) mx = fmaxf(mx, __shfl_xor_sync(~0u, mx, o));
            float sum = 0.f;
#pragma unroll
            for (int k = lane; k < 224; k += 32) {
                float e = expf(__half2float(p[k]) - mx);
                p[k] = __float2half(e);
                sum += e;
            }
#pragma unroll
            for (int o = 16; o; o >>= 1) sum += __shfl_xor_sync(~0u, sum, o);
            float inv = 1.f / sum;
#pragma unroll
            for (int k = lane; k < 224; k += 32)
                p[k] = __float2half(__half2float(p[k]) * inv);
        }
        __syncthreads();

        int wnD = (w >> 2) * 64;
        float acc3[8][4];
#pragma unroll
        for (int j = 0; j < 8; j++)
#pragma unroll
            for (int q = 0; q < 4; q++) acc3[j][q] = 0.f;

        const uint32_t* Scw = (const uint32_t*)Sc;
        const uint32_t* Vtw = (const uint32_t*)Vt;
        for (int vt = 0; vt < 7; vt++) {
            int vbase = vt * 32;
#pragma unroll
            for (int u = 0; u < 2; u++) {
                int f = tid + 256 * u;
                int row = f >> 4, seg = f & 15;
                int token = vbase + row;
                bool ok = token < T_;
                cp16(smem_u32(Ks + row * LQ + seg * 8),
                     qkv + (size_t)(b * T_ + (ok ? token : 0)) * QKVW + voff + seg * 8, ok);
            }
            CP_COMMIT();
            CP_WAIT0();
            __syncthreads();
#pragma unroll
            for (int u = 0; u < 8; u++) {
                int idx = tid + 256 * u;
                int tp = idx & 15;
                int d  = idx >> 4;
                uint32_t lo = *(const uint16_t*)(Ks + (2 * tp) * LQ + d);
                uint32_t hi = *(const uint16_t*)(Ks + (2 * tp + 1) * LQ + d);
                *(uint32_t*)(Vt + d * LVT + 2 * tp) = lo | (hi << 16);
            }
            __syncthreads();
#pragma unroll
            for (int ks = 0; ks < 2; ks++) {
                const uint32_t* ap = Scw + (wm16 + g) * 116 + vt * 16 + ks * 8;
                const uint32_t* ap8 = ap + 8 * 116;
                uint32_t a0 = ap[c], a1 = ap8[c], a2 = ap[c + 4], a3 = ap8[c + 4];
#pragma unroll
                for (int nt = 0; nt < 8; nt++) {
                    const uint32_t* bp = Vtw + (wnD + nt * 8 + g) * 20 + ks * 8;
                    MMAH(acc3[nt], a0, a1, a2, a3, bp[c], bp[c + 4]);
                }
            }
            __syncthreads();
        }

#pragma unroll
        for (int nt = 0; nt < 8; nt++) {
            int cb = wnD + nt * 8 + 2 * c;
#pragma unroll
            for (int hf = 0; hf < 2; hf++) {
                int r = wm16 + g + hf * 8;
                if (r < nq) {
                    *(__half2*)(ctx + (size_t)(b * T_ + qbase + r) * D_ + h * DK_ + cb) =
                        __floats2half2_rn(acc3[nt][hf * 2 + 0], acc3[nt][hf * 2 + 1]);
                }
            }
        }
    }
}

// ---------------- launch ------------------------------------------------------
extern "C" void kernel_launch(void* const* d_in, const int* in_sizes, int n_in,
                              void* d_out, int out_size) {
    const float* x     = (const float*)d_in[0];
    const float* masks = (const float*)d_in[1];
    const float* ln0_w = (const float*)d_in[2];
    const float* ln0_b = (const float*)d_in[3];
    const float* ln1_w = (const float*)d_in[4];
    const float* ln1_b = (const float*)d_in[5];
    const float* qkv_w = (const float*)d_in[6];
    const float* qkv_b = (const float*)d_in[7];
    const float* out_w = (const float*)d_in[8];
    const float* out_b = (const float*)d_in[9];
    const float* fsmn_w= (const float*)d_in[10];
    const float* w1    = (const float*)d_in[11];
    const float* b1    = (const float*)d_in[12];
    const float* w2    = (const float*)d_in[13];
    const float* b2    = (const float*)d_in[14];
    float* out = (float*)d_out;

    __half *h, *qkv, *vm, *fsmn, *ctx, *mid, *qkv_wt, *out_wt, *w1t, *w2t;
    float *x1;
    cudaGetSymbolAddress((void**)&h,      g_h);
    cudaGetSymbolAddress((void**)&qkv,    g_qkv);
    cudaGetSymbolAddress((void**)&vm,     g_vm);
    cudaGetSymbolAddress((void**)&fsmn,   g_fsmn);
    cudaGetSymbolAddress((void**)&ctx,    g_ctx);
    cudaGetSymbolAddress((void**)&x1,     g_x1);
    cudaGetSymbolAddress((void**)&mid,    g_mid);
    cudaGetSymbolAddress((void**)&qkv_wt, g_qkv_wt);
    cudaGetSymbolAddress((void**)&out_wt, g_out_wt);
    cudaGetSymbolAddress((void**)&w1t,    g_w1t);
    cudaGetSymbolAddress((void**)&w2t,    g_w2t);

    cudaFuncSetAttribute(hgemm, cudaFuncAttributeMaxDynamicSharedMemorySize, DSMEM_BYTES);
    cudaFuncSetAttribute(conv_att, cudaFuncAttributeMaxDynamicSharedMemorySize, DSMEM_BYTES);

    // prep: 3200 weight blocks + 1744 LN0 blocks
    prep_kernel<<<4944, 256>>>(qkv_w, out_w, w1, w2, fsmn_w, x, ln0_w, ln0_b);

    hgemm<<<dim3(QKVW / 128, R_ / 128), 256, DSMEM_BYTES>>>(h, qkv_wt, qkv_b, nullptr, qkv,
                                                            QKVW, D_, 5, masks, nullptr, vm);

    conv_att<<<CONVBLKS + 4 * B_ * H_, 256, DSMEM_BYTES>>>(vm, qkv, masks, fsmn, ctx);

    // out proj + half(fsmn) + x
    hgemm<<<dim3(D_ / 128, R_ / 128), 256, DSMEM_BYTES>>>(ctx, out_wt, out_b, x1, nullptr,
                                                          D_, D_, 2, (const float*)fsmn, x, nullptr);

    ln_kernel<<<R_ / 8, 256>>>(x1, ln1_w, ln1_b, h);

    hgemm<<<dim3(2048 / 128, R_ / 128), 256, DSMEM_BYTES>>>(h, w1t, b1, nullptr, mid,
                                                            2048, D_, 1, nullptr, nullptr, nullptr);
    hgemm<<<dim3(D_ / 128, R_ / 128), 256, DSMEM_BYTES>>>(mid, w2t, b2, out, nullptr,
                                                          D_, 2048, 3, x1, nullptr, nullptr);
    (void)in_sizes; (void)n_in; (void)out_size;
}